// round 10
// baseline (speedup 1.0000x reference)
#include <cuda_runtime.h>
#include <cuda_fp16.h>
#include <math.h>
#include <stdint.h>

#define W_ 192
#define H_ 192
#define D_ 160
#define HW_ (H_ * W_)
#define CHUNK 80
#define NPAIRS  42
#define NBLOCKS (6 * 12 * 4)

#define NTHREADS 256
#define NPROD    128

#define BAR_FULL0  1
#define BAR_FULL1  2
#define BAR_EMPTY0 3
#define BAR_EMPTY1 4
#define BAR_PROD   5

// tile geometry: 32 x 16 outputs, halo 36 x 20
#define HROWS 20
#define TROWF 800              /* floats per img plane: 20*40 */
#define TPLANEF 1600           /* floats per plane (2 imgs) */
#define TPAIRF 3200            /* floats per pair buffer */
#define RSCHH2 320             /* rs channel stride in half2: 20*16 */
#define RSPLANEH2 1600         /* rs plane stride in half2: 5*320 */
#define NXITEM 160             /* 20 rows * 8 groups */
#define NPAIRS_LD 720          /* 20*18*2 8B pairs per plane */

__device__ double   g_acc;
__device__ unsigned g_cnt;

static __device__ __forceinline__ void bar_sync_n(int id, int cnt) {
    asm volatile("bar.sync %0, %1;" :: "r"(id), "r"(cnt) : "memory");
}
static __device__ __forceinline__ void bar_arrive_n(int id, int cnt) {
    asm volatile("bar.arrive %0, %1;" :: "r"(id), "r"(cnt) : "memory");
}
static __device__ __forceinline__ void cp_async8(uint32_t dst, const float* src,
                                                 unsigned srcsz) {
    asm volatile("cp.async.ca.shared.global [%0], [%1], 8, %2;"
                 :: "r"(dst), "l"(src), "r"(srcsz) : "memory");
}
static __device__ __forceinline__ void cp_commit() {
    asm volatile("cp.async.commit_group;" ::: "memory");
}
static __device__ __forceinline__ void cp_wait2() {
    asm volatile("cp.async.wait_group 2;" ::: "memory");
}

__global__ void __launch_bounds__(NTHREADS, 2)
lncc_k(const float* __restrict__ src, const float* __restrict__ tgt,
       float* __restrict__ out)
{
    // tile: 3 pair-buffers x 2 planes x [img][haloRow(20)][col(36 pad 40)] fp32
    __shared__ float tile[3][2][2][HROWS][40];
    // rs: 2 buffers x 2 planes x [ch(5)][haloRow(20)][x(32)] fp16
    __shared__ __align__(16) __half2 rs[2][2][5][HROWS][16];
    __shared__ float wsum[8];

    const int tid = threadIdx.x;
    const int x0  = blockIdx.x * 32;
    const int y0  = blockIdx.y * 16;
    const int b   = blockIdx.z >> 1;
    const int z0  = (blockIdx.z & 1) * CHUNK;
    const int zstart = z0 - 2;

    const float* baseS = src + (size_t)b * (D_ * HW_);
    const float* baseT = tgt + (size_t)b * (D_ * HW_);

    float acc = 0.f;

    if (tid < NPROD) {
        // ========================= PRODUCER (128) =========================
        // Halo plane: 36 cols x 20 rows x 2 imgs = 720 8B pairs (18/row).
        // Slot sl covers pair index i = tid + 128*sl, sl = 0..5 (sl=5: tid<80).
        uint32_t soffb[6];
        const float* gbase[6];
        unsigned vmask = 0;   // bit sl: used AND xy-valid
        unsigned umask = 0;   // bit sl: used
        #pragma unroll
        for (int sl = 0; sl < 6; sl++) {
            soffb[sl] = 0; gbase[sl] = baseS;
            const int i = tid + NPROD * sl;
            if (i < NPAIRS_LD) {
                umask |= 1u << sl;
                const int img = (i >= 360) ? 1 : 0;
                const int j   = i - img * 360;
                const int row = j / 18;
                const int pc  = j - row * 18;
                soffb[sl] = (uint32_t)(img * TROWF + row * 40 + pc * 2) * 4u;
                const int gy = y0 + row - 2;
                const int gx = x0 + pc * 2 - 2;  // even; pairs never straddle W
                const bool v = ((unsigned)gy < (unsigned)H_) &&
                               ((unsigned)gx < (unsigned)W_);
                if (v) vmask |= 1u << sl;
                gbase[sl] = (img ? baseT : baseS) + (v ? (gy * W_ + gx) : 0);
            }
        }

        const uint32_t sbase =
            (uint32_t)__cvta_generic_to_shared(&tile[0][0][0][0][0]);

        auto issue_pair = [&](int m) {          // planes 2m,2m+1 -> pairbuf m%3
            const uint32_t pb = sbase + (uint32_t)(m % 3) * (TPAIRF * 4u);
            #pragma unroll
            for (int pl = 0; pl < 2; pl++) {
                const int zp   = zstart + 2 * m + pl;
                const bool zin = (unsigned)zp < (unsigned)D_;
                const int zoff = zin ? zp * HW_ : 0;
                const uint32_t tb = pb + (uint32_t)pl * (TPLANEF * 4u);
                #pragma unroll
                for (int sl = 0; sl < 6; sl++) {
                    if (umask & (1u << sl)) {
                        unsigned sz = (zin && (vmask & (1u << sl))) ? 8u : 0u;
                        cp_async8(tb + soffb[sl], gbase[sl] + zoff, sz);
                    }
                }
            }
            cp_commit();
        };

        // pack 4 fp32 windows -> 2 half2, single 8B store
        auto st_h4 = [](__half2* dst, float a, float b2, float c, float d) {
            union { __half2 h[2]; uint2 u; } pk;
            pk.h[0] = __floats2half2_rn(a, b2);
            pk.h[1] = __floats2half2_rn(c, d);
            *(uint2*)dst = pk.u;
        };

        // x-phase for one item (r, x4): tile plane tb -> rs plane rsq (fp16)
        auto xitem = [&](const float* tb, __half2* rsq, int item) {
            const int r  = item >> 3;
            const int x4 = (item & 7) << 2;
            const float* rowS = tb + r * 40 + x4;
            const float* rowT = rowS + TROWF;
            float4 a0 = *(const float4*)(rowS);
            float4 a1 = *(const float4*)(rowS + 4);
            float4 b0 = *(const float4*)(rowT);
            float4 b1 = *(const float4*)(rowT + 4);
            float sc[8] = {a0.x,a0.y,a0.z,a0.w,a1.x,a1.y,a1.z,a1.w};
            float tc[8] = {b0.x,b0.y,b0.z,b0.w,b1.x,b1.y,b1.z,b1.w};
            const int ro = r * 16 + (x4 >> 1);   // half2 offset within channel
            {
                float S0=0.f, T0=0.f;
                #pragma unroll
                for (int j = 0; j < 5; j++) { S0 += sc[j]; T0 += tc[j]; }
                float Sv[4], Tv[4];
                Sv[0]=S0; Tv[0]=T0;
                #pragma unroll
                for (int w = 1; w < 4; w++) {
                    Sv[w] = Sv[w-1] - sc[w-1] + sc[w+4];
                    Tv[w] = Tv[w-1] - tc[w-1] + tc[w+4];
                }
                st_h4(rsq + 0*RSCHH2 + ro, Sv[0],Sv[1],Sv[2],Sv[3]);
                st_h4(rsq + 1*RSCHH2 + ro, Tv[0],Tv[1],Tv[2],Tv[3]);
            }
            {
                float SS0=0.f, TT0=0.f;
                #pragma unroll
                for (int j = 0; j < 5; j++) {
                    SS0 = fmaf(sc[j], sc[j], SS0);
                    TT0 = fmaf(tc[j], tc[j], TT0);
                }
                float SSv[4], TTv[4];
                SSv[0]=SS0; TTv[0]=TT0;
                #pragma unroll
                for (int w = 1; w < 4; w++) {
                    SSv[w] = SSv[w-1] - sc[w-1]*sc[w-1] + sc[w+4]*sc[w+4];
                    TTv[w] = TTv[w-1] - tc[w-1]*tc[w-1] + tc[w+4]*tc[w+4];
                }
                st_h4(rsq + 2*RSCHH2 + ro, SSv[0],SSv[1],SSv[2],SSv[3]);
                st_h4(rsq + 3*RSCHH2 + ro, TTv[0],TTv[1],TTv[2],TTv[3]);
            }
            {
                float ST0=0.f;
                #pragma unroll
                for (int j = 0; j < 5; j++) ST0 = fmaf(sc[j], tc[j], ST0);
                float STv[4];
                STv[0]=ST0;
                #pragma unroll
                for (int w = 1; w < 4; w++)
                    STv[w] = STv[w-1] - sc[w-1]*tc[w-1] + sc[w+4]*tc[w+4];
                st_h4(rsq + 4*RSCHH2 + ro, STv[0],STv[1],STv[2],STv[3]);
            }
        };

        issue_pair(0);
        issue_pair(1);

        for (int k = 0; k < NPAIRS; k++) {
            const int q = k & 1;
            bar_sync_n(BAR_EMPTY0 + q, NTHREADS);
            issue_pair(k + 2);
            cp_wait2();                          // pair k's group has landed
            bar_sync_n(BAR_PROD, NPROD);         // cross-thread visibility

            {
                const float* pb = &tile[k % 3][0][0][0][0];
                __half2* rq = &rs[q][0][0][0][0];
                xitem(pb,           rq,             tid);   // plane 2k
                xitem(pb + TPLANEF, rq + RSPLANEH2, tid);   // plane 2k+1
                if (tid < 32) {
                    xitem(pb,           rq,             128 + tid);
                    xitem(pb + TPLANEF, rq + RSPLANEH2, 128 + tid);
                }
            }
            bar_arrive_n(BAR_FULL0 + q, NTHREADS);  // rs[q] published (pair k)
        }
    } else {
        // ========================= CONSUMER (128) =========================
        // thread owns 4 px: x-pair (2*cx2, 2*cx2+1), y-rows (2*cyp, 2*cyp+1)
        const int ctid = tid - NPROD;
        const int cx2  = ctid & 15;              // 0..15 x-pair
        const int cyp  = ctid >> 4;              // 0..7  y-pair
        const int cbase = (2 * cyp) * 16 + cx2;  // half2 index of top halo row

        // z-ring: half2 delay line (x-packed), run: fp32 per px
        __half2 ring[5][2][5];
        float2  run[2][5];
        const __half2 hz = __floats2half2_rn(0.f, 0.f);
        #pragma unroll
        for (int s = 0; s < 5; s++)
            #pragma unroll
            for (int r = 0; r < 2; r++)
                #pragma unroll
                for (int c = 0; c < 5; c++) ring[s][r][c] = hz;
        #pragma unroll
        for (int r = 0; r < 2; r++)
            #pragma unroll
            for (int c = 0; c < 5; c++) run[r][c] = make_float2(0.f, 0.f);

        bar_arrive_n(BAR_EMPTY0, NTHREADS);
        bar_arrive_n(BAR_EMPTY1, NTHREADS);

        // one plane of consumer work; s = ring slot (compile-time)
        auto consume_plane = [&](const __half2* rp, int s, bool live) {
            #pragma unroll
            for (int c = 0; c < 5; c++) {
                const __half2* col = rp + c * RSCHH2 + cbase;
                __half2 v0 = col[0*16];
                __half2 v1 = col[1*16];
                __half2 v2 = col[2*16];
                __half2 v3 = col[3*16];
                __half2 v4 = col[4*16];
                __half2 v5 = col[5*16];
                __half2 n0 = __hadd2(__hadd2(__hadd2(v0, v1), __hadd2(v2, v3)), v4);
                __half2 n1 = __hadd2(__hsub2(n0, v0), v5);
                float2 f0 = __half22float2(n0);
                float2 f1 = __half22float2(n1);
                float2 o0 = __half22float2(ring[s][0][c]);
                float2 o1 = __half22float2(ring[s][1][c]);
                run[0][c].x += f0.x - o0.x;  run[0][c].y += f0.y - o0.y;
                run[1][c].x += f1.x - o1.x;  run[1][c].y += f1.y - o1.y;
                ring[s][0][c] = n0;
                ring[s][1][c] = n1;
            }
            if (live) {
                const float inv = 1.f / 125.f;
                #pragma unroll
                for (int r = 0; r < 2; r++) {
                    #pragma unroll
                    for (int e = 0; e < 2; e++) {
                        float rS  = e ? run[r][0].y : run[r][0].x;
                        float rT  = e ? run[r][1].y : run[r][1].x;
                        float rSS = e ? run[r][2].y : run[r][2].x;
                        float rTT = e ? run[r][3].y : run[r][3].x;
                        float rST = e ? run[r][4].y : run[r][4].x;
                        float sm = rS * inv;
                        float tm = rT * inv;
                        float sv = fmaf(-sm, sm, rSS * inv);
                        float tv = fmaf(-tm, tm, rTT * inv);
                        float cr = fmaf(-sm, tm, rST * inv);
                        float den = fmaf(sv, tv, 1e-5f);
                        acc += __fdividef(cr * cr, den);
                    }
                }
            }
        };

        for (int kb = 0; kb < 45; kb += 5) {
            #pragma unroll
            for (int jj = 0; jj < 5; jj++) {     // compile-time slot pattern
                const int k = kb + jj;
                if (k >= NPAIRS) break;          // 42 = 8*5 + 2
                const int q  = k & 1;
                const int s0 = (2 * jj) % 5;
                const int s1 = (2 * jj + 1) % 5;
                bar_sync_n(BAR_FULL0 + q, NTHREADS);

                const __half2* rq = &rs[q][0][0][0][0];
                consume_plane(rq,             s0, k >= 2);  // plane 2k
                consume_plane(rq + RSPLANEH2, s1, k >= 2);  // plane 2k+1

                bar_arrive_n(BAR_EMPTY0 + q, NTHREADS);
            }
        }
    }

    // ---- block reduction over all 256 threads (producers contribute 0) ----
    __syncthreads();
    #pragma unroll
    for (int o = 16; o > 0; o >>= 1)
        acc += __shfl_xor_sync(0xffffffffu, acc, o);
    if ((tid & 31) == 0) wsum[tid >> 5] = acc;
    __syncthreads();

    if (tid == 0) {
        float bsum = 0.f;
        #pragma unroll
        for (int i = 0; i < 8; i++) bsum += wsum[i];
        atomicAdd(&g_acc, (double)bsum);
        __threadfence();
        unsigned done = atomicAdd(&g_cnt, 1u);
        if (done == NBLOCKS - 1) {
            double total = atomicAdd(&g_acc, 0.0);  // fenced read
            const double n = 2.0 * 160.0 * 192.0 * 192.0;
            float loss = (float)(1.0 - total / n);
            if (isnan(loss) || isinf(loss)) loss = 1.0f;
            out[0] = loss;
            *((volatile double*)&g_acc)   = 0.0;
            *((volatile unsigned*)&g_cnt) = 0u;
        }
    }
}

extern "C" void kernel_launch(void* const* d_in, const int* in_sizes, int n_in,
                              void* d_out, int out_size)
{
    (void)in_sizes; (void)n_in; (void)out_size;
    const float* src = (const float*)d_in[0];
    const float* tgt = (const float*)d_in[1];

    lncc_k<<<dim3(6, 12, 4), NTHREADS>>>(src, tgt, (float*)d_out);
}

// round 11
// speedup vs baseline: 1.1231x; 1.1231x over previous
#include <cuda_runtime.h>
#include <cuda_fp16.h>
#include <math.h>
#include <stdint.h>

#define W_ 192
#define H_ 192
#define D_ 160
#define HW_ (H_ * W_)
#define CHUNK 80
#define NPAIRS  42
#define NBLOCKS (6 * 24 * 4)

#define NTHREADS 256
#define NPROD    128

#define BAR_FULL0  1
#define BAR_FULL1  2
#define BAR_EMPTY0 3
#define BAR_EMPTY1 4
#define BAR_PROD   5

// tile geometry: 32 x 8 outputs, halo 36 x 12
#define HROWS 12
#define TROWF 480              /* floats per img plane: 12*40 */
#define TPLANEF 960            /* floats per plane (2 imgs) */
#define TPAIRF 1920            /* floats per pair buffer */
#define NPAIRS_LD 432          /* 12*18*2 8B pairs per plane */

// rs layout (plane-interleaved): [ch(5)][row(12)][x2(16)][plane(2)] of __half2
#define RSCH 384               /* ch stride in half2: 12*16*2 */
#define RSROW 32               /* row stride in half2 */
#define RSQ 1920               /* per-q stride in half2: 5*384 */

__device__ double   g_acc;
__device__ unsigned g_cnt;

static __device__ __forceinline__ void bar_sync_n(int id, int cnt) {
    asm volatile("bar.sync %0, %1;" :: "r"(id), "r"(cnt) : "memory");
}
static __device__ __forceinline__ void bar_arrive_n(int id, int cnt) {
    asm volatile("bar.arrive %0, %1;" :: "r"(id), "r"(cnt) : "memory");
}
static __device__ __forceinline__ void cp_async8(uint32_t dst, const float* src,
                                                 unsigned srcsz) {
    asm volatile("cp.async.ca.shared.global [%0], [%1], 8, %2;"
                 :: "r"(dst), "l"(src), "r"(srcsz) : "memory");
}
static __device__ __forceinline__ void cp_commit() {
    asm volatile("cp.async.commit_group;" ::: "memory");
}
static __device__ __forceinline__ void cp_wait2() {
    asm volatile("cp.async.wait_group 2;" ::: "memory");
}
// 8B shared load of two adjacent half2 (plane0, plane1)
static __device__ __forceinline__ void lds_h2x2(const __half2* p,
                                                __half2& a, __half2& b) {
    uint2 u = *reinterpret_cast<const uint2*>(p);
    a = *reinterpret_cast<__half2*>(&u.x);
    b = *reinterpret_cast<__half2*>(&u.y);
}

__global__ void __launch_bounds__(NTHREADS, 2)
lncc_k(const float* __restrict__ src, const float* __restrict__ tgt,
       float* __restrict__ out)
{
    // tile: 3 pair-buffers x 2 planes x [img][haloRow(12)][col(36 pad 40)] fp32
    __shared__ float tile[3][2][2][HROWS][40];
    // rs: 2 buffers, plane-interleaved fp16 (see RSCH/RSROW)
    __shared__ __align__(16) __half2 rs[2][RSQ];
    __shared__ float wsum[8];

    const int tid = threadIdx.x;
    const int x0  = blockIdx.x * 32;
    const int y0  = blockIdx.y * 8;
    const int b   = blockIdx.z >> 1;
    const int z0  = (blockIdx.z & 1) * CHUNK;
    const int zstart = z0 - 2;

    const float* baseS = src + (size_t)b * (D_ * HW_);
    const float* baseT = tgt + (size_t)b * (D_ * HW_);

    float acc = 0.f;

    if (tid < NPROD) {
        // ========================= PRODUCER (128) =========================
        uint32_t soffb[4];
        const float* gbase[4];
        unsigned vmask = 0, umask = 0;
        #pragma unroll
        for (int sl = 0; sl < 4; sl++) {
            soffb[sl] = 0; gbase[sl] = baseS;
            const int i = tid + NPROD * sl;
            if (i < NPAIRS_LD) {
                umask |= 1u << sl;
                const int img = (i >= 216) ? 1 : 0;
                const int j   = i - img * 216;
                const int row = j / 18;
                const int pc  = j - row * 18;
                soffb[sl] = (uint32_t)(img * TROWF + row * 40 + pc * 2) * 4u;
                const int gy = y0 + row - 2;
                const int gx = x0 + pc * 2 - 2;
                const bool v = ((unsigned)gy < (unsigned)H_) &&
                               ((unsigned)gx < (unsigned)W_);
                if (v) vmask |= 1u << sl;
                gbase[sl] = (img ? baseT : baseS) + (v ? (gy * W_ + gx) : 0);
            }
        }

        const uint32_t sbase =
            (uint32_t)__cvta_generic_to_shared(&tile[0][0][0][0][0]);

        auto issue_pair = [&](int m) {
            const uint32_t pb = sbase + (uint32_t)(m % 3) * (TPAIRF * 4u);
            #pragma unroll
            for (int pl = 0; pl < 2; pl++) {
                const int zp   = zstart + 2 * m + pl;
                const bool zin = (unsigned)zp < (unsigned)D_;
                const int zoff = zin ? zp * HW_ : 0;
                const uint32_t tb = pb + (uint32_t)pl * (TPLANEF * 4u);
                #pragma unroll
                for (int sl = 0; sl < 4; sl++) {
                    if (umask & (1u << sl)) {
                        unsigned sz = (zin && (vmask & (1u << sl))) ? 8u : 0u;
                        cp_async8(tb + soffb[sl], gbase[sl] + zoff, sz);
                    }
                }
            }
            cp_commit();
        };

        // x-phase item covering BOTH planes of (row r, group g): 4 windows,
        // packs plane0+plane1 per channel into one 16B store.
        auto xpair = [&](const float* pbuf, __half2* rsq, int item) {
            const int r = item >> 3;
            const int g = item & 7;
            const float* base0 = pbuf + r * 40 + 4 * g;
            __half2 keep[5][2];           // plane0 packed windows per channel
            #pragma unroll
            for (int pl = 0; pl < 2; pl++) {
                const float* rowS = base0 + pl * TPLANEF;
                const float* rowT = rowS + TROWF;
                float4 a0 = *(const float4*)(rowS);
                float4 a1 = *(const float4*)(rowS + 4);
                float4 b0 = *(const float4*)(rowT);
                float4 b1 = *(const float4*)(rowT + 4);
                float sc[8] = {a0.x,a0.y,a0.z,a0.w,a1.x,a1.y,a1.z,a1.w};
                float tc[8] = {b0.x,b0.y,b0.z,b0.w,b1.x,b1.y,b1.z,b1.w};

                float V[5][4];
                {
                    float S0=0.f, T0=0.f, SS0=0.f, TT0=0.f, ST0=0.f;
                    #pragma unroll
                    for (int j = 0; j < 5; j++) {
                        S0 += sc[j]; T0 += tc[j];
                        SS0 = fmaf(sc[j], sc[j], SS0);
                        TT0 = fmaf(tc[j], tc[j], TT0);
                        ST0 = fmaf(sc[j], tc[j], ST0);
                    }
                    V[0][0]=S0; V[1][0]=T0; V[2][0]=SS0; V[3][0]=TT0; V[4][0]=ST0;
                    #pragma unroll
                    for (int w = 1; w < 4; w++) {
                        V[0][w] = V[0][w-1] - sc[w-1] + sc[w+4];
                        V[1][w] = V[1][w-1] - tc[w-1] + tc[w+4];
                        V[2][w] = V[2][w-1] - sc[w-1]*sc[w-1] + sc[w+4]*sc[w+4];
                        V[3][w] = V[3][w-1] - tc[w-1]*tc[w-1] + tc[w+4]*tc[w+4];
                        V[4][w] = V[4][w-1] - sc[w-1]*tc[w-1] + sc[w+4]*tc[w+4];
                    }
                }
                if (pl == 0) {
                    #pragma unroll
                    for (int c = 0; c < 5; c++) {
                        keep[c][0] = __floats2half2_rn(V[c][0], V[c][1]);
                        keep[c][1] = __floats2half2_rn(V[c][2], V[c][3]);
                    }
                } else {
                    #pragma unroll
                    for (int c = 0; c < 5; c++) {
                        union { __half2 h[4]; uint4 u; } pk;
                        pk.h[0] = keep[c][0];
                        pk.h[1] = __floats2half2_rn(V[c][0], V[c][1]);
                        pk.h[2] = keep[c][1];
                        pk.h[3] = __floats2half2_rn(V[c][2], V[c][3]);
                        *reinterpret_cast<uint4*>(rsq + c * RSCH + r * RSROW + 4 * g)
                            = pk.u;
                    }
                }
            }
        };

        issue_pair(0);
        issue_pair(1);

        for (int k = 0; k < NPAIRS; k++) {
            const int q = k & 1;
            bar_sync_n(BAR_EMPTY0 + q, NTHREADS);
            issue_pair(k + 2);
            cp_wait2();
            bar_sync_n(BAR_PROD, NPROD);

            if (tid < 96)
                xpair(&tile[k % 3][0][0][0][0], &rs[q][0], tid);

            bar_arrive_n(BAR_FULL0 + q, NTHREADS);
        }
    } else {
        // ========================= CONSUMER (128) =========================
        // thread owns x-pair (2*ctx2, 2*ctx2+1) at output row cty
        const int ctid = tid - NPROD;
        const int ctx2 = ctid & 15;
        const int cty  = ctid >> 4;

        float2 ring[5][5];      // [slot][ch], x-pair packed
        float2 run[5];
        #pragma unroll
        for (int s = 0; s < 5; s++)
            #pragma unroll
            for (int c = 0; c < 5; c++) ring[s][c] = make_float2(0.f, 0.f);
        #pragma unroll
        for (int c = 0; c < 5; c++) run[c] = make_float2(0.f, 0.f);

        bar_arrive_n(BAR_EMPTY0, NTHREADS);
        bar_arrive_n(BAR_EMPTY1, NTHREADS);

        const int cbase = cty * RSROW + ctx2 * 2;

        auto epilogue = [&]() {
            const float inv = 1.f / 125.f;
            #pragma unroll
            for (int e = 0; e < 2; e++) {
                float rS  = e ? run[0].y : run[0].x;
                float rT  = e ? run[1].y : run[1].x;
                float rSS = e ? run[2].y : run[2].x;
                float rTT = e ? run[3].y : run[3].x;
                float rST = e ? run[4].y : run[4].x;
                float sm = rS * inv;
                float tm = rT * inv;
                float sv = fmaf(-sm, sm, rSS * inv);
                float tv = fmaf(-tm, tm, rTT * inv);
                float cr = fmaf(-sm, tm, rST * inv);
                float den = fmaf(sv, tv, 1e-5f);
                acc += __fdividef(cr * cr, den);
            }
        };

        // consume both planes of pair k; slots s0 (plane 2k), s1 (plane 2k+1)
        auto consume_pair = [&](const __half2* rq, int s0, int s1, bool live) {
            __half2 stash1[5];
            #pragma unroll
            for (int c = 0; c < 5; c++) {
                const __half2* col = rq + c * RSCH + cbase;
                __half2 p0, p1, q0, q1;
                lds_h2x2(col + 0 * RSROW, p0, p1);
                lds_h2x2(col + 1 * RSROW, q0, q1);
                __half2 n0 = __hadd2(p0, q0);
                __half2 n1 = __hadd2(p1, q1);
                lds_h2x2(col + 2 * RSROW, p0, p1);
                lds_h2x2(col + 3 * RSROW, q0, q1);
                n0 = __hadd2(n0, __hadd2(p0, q0));
                n1 = __hadd2(n1, __hadd2(p1, q1));
                lds_h2x2(col + 4 * RSROW, p0, p1);
                n0 = __hadd2(n0, p0);
                n1 = __hadd2(n1, p1);
                // plane 2k ring update (slot s0)
                float2 f0 = __half22float2(n0);
                float2 o0 = ring[s0][c];
                run[c].x += f0.x - o0.x;
                run[c].y += f0.y - o0.y;
                ring[s0][c] = f0;
                stash1[c] = n1;
            }
            if (live) epilogue();            // plane 2k
            #pragma unroll
            for (int c = 0; c < 5; c++) {
                float2 f1 = __half22float2(stash1[c]);
                float2 o1 = ring[s1][c];
                run[c].x += f1.x - o1.x;
                run[c].y += f1.y - o1.y;
                ring[s1][c] = f1;
            }
            if (live) epilogue();            // plane 2k+1
        };

        for (int kb = 0; kb < 45; kb += 5) {
            #pragma unroll
            for (int jj = 0; jj < 5; jj++) {
                const int k = kb + jj;
                if (k >= NPAIRS) break;      // 42 = 8*5 + 2
                const int q  = k & 1;
                const int s0 = (2 * jj) % 5;
                const int s1 = (2 * jj + 1) % 5;
                bar_sync_n(BAR_FULL0 + q, NTHREADS);
                consume_pair(&rs[q][0], s0, s1, k >= 2);
                bar_arrive_n(BAR_EMPTY0 + q, NTHREADS);
            }
        }
    }

    // ---- block reduction over all 256 threads (producers contribute 0) ----
    __syncthreads();
    #pragma unroll
    for (int o = 16; o > 0; o >>= 1)
        acc += __shfl_xor_sync(0xffffffffu, acc, o);
    if ((tid & 31) == 0) wsum[tid >> 5] = acc;
    __syncthreads();

    if (tid == 0) {
        float bsum = 0.f;
        #pragma unroll
        for (int i = 0; i < 8; i++) bsum += wsum[i];
        atomicAdd(&g_acc, (double)bsum);
        __threadfence();
        unsigned done = atomicAdd(&g_cnt, 1u);
        if (done == NBLOCKS - 1) {
            double total = atomicAdd(&g_acc, 0.0);  // fenced read
            const double n = 2.0 * 160.0 * 192.0 * 192.0;
            float loss = (float)(1.0 - total / n);
            if (isnan(loss) || isinf(loss)) loss = 1.0f;
            out[0] = loss;
            *((volatile double*)&g_acc)   = 0.0;
            *((volatile unsigned*)&g_cnt) = 0u;
        }
    }
}

extern "C" void kernel_launch(void* const* d_in, const int* in_sizes, int n_in,
                              void* d_out, int out_size)
{
    (void)in_sizes; (void)n_in; (void)out_size;
    const float* src = (const float*)d_in[0];
    const float* tgt = (const float*)d_in[1];

    lncc_k<<<dim3(6, 24, 4), NTHREADS>>>(src, tgt, (float*)d_out);
}